// round 1
// baseline (speedup 1.0000x reference)
#include <cuda_runtime.h>

// Problem constants (fixed by the reference)
#define NV   400000
#define CIN  64
#define COUT 64
#define KT   27
#define TILE 64      // voxels per block

// ---- packed f32x2 helpers (sm_103a FFMA2 path) ----
__device__ __forceinline__ unsigned long long pack2(float lo, float hi) {
    unsigned long long r;
    asm("mov.b64 %0, {%1, %2};" : "=l"(r) : "f"(lo), "f"(hi));
    return r;
}
__device__ __forceinline__ void unpack2(unsigned long long v, float& lo, float& hi) {
    asm("mov.b64 {%0, %1}, %2;" : "=f"(lo), "=f"(hi) : "l"(v));
}
__device__ __forceinline__ void ffma2(unsigned long long& d,
                                      unsigned long long a,
                                      unsigned long long b) {
    asm("fma.rn.f32x2 %0, %1, %2, %0;" : "+l"(d) : "l"(a), "l"(b));
}

// Block: 256 threads = 16 (cout groups) x 16 (voxel groups).
// Each thread computes 4 voxels x 4 couts, accumulated as 8 packed f32x2.
__global__ __launch_bounds__(256, 4)
void spconv64_kernel(const float* __restrict__ feats,
                     const float* __restrict__ weight,
                     const float* __restrict__ bias,
                     const int*   __restrict__ nbr,
                     float*       __restrict__ out)
{
    __shared__ float Ws[64][68];   // [cin][cout], +4 pad keeps 16B align + kills conflicts
    __shared__ float Fs[64][68];   // [voxel][cin]

    const int tid   = threadIdx.x;
    const int jbase = blockIdx.x * TILE;
    const int cg = tid & 15;       // cout group 0..15
    const int vg = tid >> 4;       // voxel group 0..15
    const int c0 = cg * 4;
    const int v0 = vg * 4;

    // accumulators initialized with bias
    unsigned long long acc[4][2];
    {
        const unsigned long long b01 = pack2(__ldg(&bias[c0]),     __ldg(&bias[c0 + 1]));
        const unsigned long long b23 = pack2(__ldg(&bias[c0 + 2]), __ldg(&bias[c0 + 3]));
        #pragma unroll
        for (int q = 0; q < 4; ++q) { acc[q][0] = b01; acc[q][1] = b23; }
    }

    const float4* feats4 = reinterpret_cast<const float4*>(feats);

    for (int k = 0; k < KT; ++k) {
        __syncthreads();   // previous tap's compute done reading Ws/Fs

        // ---- stage weights for tap k: 64x64 f32 = 1024 float4 ----
        const float4* wk = reinterpret_cast<const float4*>(weight + k * (CIN * COUT));
        #pragma unroll
        for (int r = 0; r < 4; ++r) {
            const int l = tid + r * 256;                 // 0..1023
            const float4 w = wk[l];
            *reinterpret_cast<float4*>(&Ws[l >> 4][(l & 15) * 4]) = w;
        }

        // ---- masked gather of 64 voxel rows (64 f32 each) ----
        const int* nk = nbr + k * NV + jbase;
        #pragma unroll
        for (int r = 0; r < 4; ++r) {
            const int l  = tid + r * 256;
            const int v  = l >> 4;                       // voxel within tile
            const int f4 = l & 15;                       // float4 chunk of the row
            const int idx = nk[v];                       // broadcast across 16 lanes
            float4 val = make_float4(0.f, 0.f, 0.f, 0.f);
            if (idx >= 0) val = feats4[idx * 16 + f4];
            *reinterpret_cast<float4*>(&Fs[v][f4 * 4]) = val;
        }
        __syncthreads();

        // ---- 64x64x64 tile GEMM, FFMA2 inner kernel ----
        #pragma unroll
        for (int i = 0; i < 64; i += 4) {
            // weight pairs loaded pre-packed straight from smem (LDS.64, no MOV packing)
            unsigned long long w0[4], w1[4];
            #pragma unroll
            for (int ii = 0; ii < 4; ++ii) {
                w0[ii] = *reinterpret_cast<const unsigned long long*>(&Ws[i + ii][c0]);
                w1[ii] = *reinterpret_cast<const unsigned long long*>(&Ws[i + ii][c0 + 2]);
            }
            #pragma unroll
            for (int q = 0; q < 4; ++q) {
                const float4 f = *reinterpret_cast<const float4*>(&Fs[v0 + q][i]);
                const unsigned long long a0 = pack2(f.x, f.x);
                const unsigned long long a1 = pack2(f.y, f.y);
                const unsigned long long a2 = pack2(f.z, f.z);
                const unsigned long long a3 = pack2(f.w, f.w);
                ffma2(acc[q][0], a0, w0[0]); ffma2(acc[q][1], a0, w1[0]);
                ffma2(acc[q][0], a1, w0[1]); ffma2(acc[q][1], a1, w1[1]);
                ffma2(acc[q][0], a2, w0[2]); ffma2(acc[q][1], a2, w1[2]);
                ffma2(acc[q][0], a3, w0[3]); ffma2(acc[q][1], a3, w1[3]);
            }
        }
    }

    // ---- epilogue: unpack and store 4 voxels x 4 couts ----
    #pragma unroll
    for (int q = 0; q < 4; ++q) {
        float4 o;
        unpack2(acc[q][0], o.x, o.y);
        unpack2(acc[q][1], o.z, o.w);
        *reinterpret_cast<float4*>(&out[(size_t)(jbase + v0 + q) * COUT + c0]) = o;
    }
}

extern "C" void kernel_launch(void* const* d_in, const int* in_sizes, int n_in,
                              void* d_out, int out_size) {
    const float* feats  = (const float*)d_in[0];   // [N, 64] f32
    const float* weight = (const float*)d_in[1];   // [27, 64, 64] f32
    const float* bias   = (const float*)d_in[2];   // [64] f32
    const int*   nbr    = (const int*)  d_in[3];   // [27, N] i32
    float*       out    = (float*)d_out;           // [N, 64] f32

    spconv64_kernel<<<NV / TILE, 256>>>(feats, weight, bias, nbr, out);
}

// round 2
// speedup vs baseline: 1.0080x; 1.0080x over previous
#include <cuda_runtime.h>

// Problem constants
#define NV      400000
#define CIN     64
#define COUT    64
#define KT      27
#define TILE    128        // voxels per block
#define THREADS 128

#define WPAD 68            // Ws row stride (floats): 272B, 16B-aligned
#define FPAD 68            // Fs row stride (floats): 272B, 16B-aligned
#define SMEM_FLOATS (64 * WPAD + TILE * FPAD)
#define SMEM_BYTES  (SMEM_FLOATS * 4)

typedef unsigned long long u64;

// ---- packed f32x2 helpers ----
__device__ __forceinline__ u64 pack2(float lo, float hi) {
    u64 r;
    asm("mov.b64 %0, {%1, %2};" : "=l"(r) : "f"(lo), "f"(hi));
    return r;
}
__device__ __forceinline__ void unpack2(u64 v, float& lo, float& hi) {
    asm("mov.b64 {%0, %1}, %2;" : "=f"(lo), "=f"(hi) : "l"(v));
}
__device__ __forceinline__ void ffma2(u64& d, u64 a, u64 b) {
    asm("fma.rn.f32x2 %0, %1, %2, %0;" : "+l"(d) : "l"(a), "l"(b));
}

// 128 threads: cg = tid&7 (8 cout-groups x 8 couts), vg = tid>>3 (16 voxel-groups x 8 voxels)
// Thread tile: 8 voxels x 8 couts = 32 packed f32x2 accumulators.
__global__ __launch_bounds__(THREADS, 4)
void spconv88_kernel(const float* __restrict__ feats,
                     const float* __restrict__ weight,
                     const float* __restrict__ bias,
                     const int*   __restrict__ nbr,
                     float*       __restrict__ out)
{
    extern __shared__ float smem[];
    float* Ws = smem;                // [64][WPAD]  weights for current tap
    float* Fs = smem + 64 * WPAD;    // [TILE][FPAD] gathered activations

    const int tid   = threadIdx.x;
    const int jbase = blockIdx.x * TILE;
    const int cg = tid & 7;
    const int vg = tid >> 3;
    const int c0 = cg * 8;
    const int v0 = vg * 8;

    // 8 voxels x 4 cout-pairs of packed accumulators, seeded with bias
    u64 acc[8][4];
    {
        u64 b[4];
        #pragma unroll
        for (int p = 0; p < 4; ++p)
            b[p] = pack2(__ldg(&bias[c0 + 2 * p]), __ldg(&bias[c0 + 2 * p + 1]));
        #pragma unroll
        for (int q = 0; q < 8; ++q)
            #pragma unroll
            for (int p = 0; p < 4; ++p)
                acc[q][p] = b[p];
    }

    const float4* feats4 = reinterpret_cast<const float4*>(feats);

    for (int k = 0; k < KT; ++k) {
        __syncthreads();   // previous tap's compute finished with Ws/Fs

        // ---- stage weights for tap k: 64x64 f32 = 1024 float4, 8 per thread ----
        const float4* wk = reinterpret_cast<const float4*>(weight + k * (CIN * COUT));
        #pragma unroll
        for (int r = 0; r < 8; ++r) {
            const int l = tid + r * THREADS;         // 0..1023
            const float4 w = wk[l];
            *reinterpret_cast<float4*>(&Ws[(l >> 4) * WPAD + (l & 15) * 4]) = w;
        }

        // ---- masked gather: thread tid owns voxel row tid (64 floats) ----
        {
            const int idx = nbr[k * NV + jbase + tid];
            float4* dst = reinterpret_cast<float4*>(&Fs[tid * FPAD]);
            if (idx >= 0) {
                const float4* src = feats4 + (size_t)idx * 16;
                #pragma unroll
                for (int f = 0; f < 16; ++f) dst[f] = src[f];
            } else {
                const float4 z = make_float4(0.f, 0.f, 0.f, 0.f);
                #pragma unroll
                for (int f = 0; f < 16; ++f) dst[f] = z;
            }
        }
        __syncthreads();

        // ---- 128x64x64 tile GEMM, 8x8 register tile, FFMA2 ----
        #pragma unroll 4
        for (int i = 0; i < 64; i += 2) {
            // weight fragments: 2 k-slices x 4 cout-pairs, loaded pre-packed
            u64 w[2][4];
            #pragma unroll
            for (int ii = 0; ii < 2; ++ii) {
                const u64* wrow = reinterpret_cast<const u64*>(&Ws[(i + ii) * WPAD + c0]);
                w[ii][0] = wrow[0]; w[ii][1] = wrow[1];
                w[ii][2] = wrow[2]; w[ii][3] = wrow[3];
            }
            #pragma unroll
            for (int q = 0; q < 8; ++q) {
                const float2 f = *reinterpret_cast<const float2*>(&Fs[(v0 + q) * FPAD + i]);
                const u64 a0 = pack2(f.x, f.x);
                const u64 a1 = pack2(f.y, f.y);
                ffma2(acc[q][0], a0, w[0][0]);
                ffma2(acc[q][1], a0, w[0][1]);
                ffma2(acc[q][2], a0, w[0][2]);
                ffma2(acc[q][3], a0, w[0][3]);
                ffma2(acc[q][0], a1, w[1][0]);
                ffma2(acc[q][1], a1, w[1][1]);
                ffma2(acc[q][2], a1, w[1][2]);
                ffma2(acc[q][3], a1, w[1][3]);
            }
        }
    }

    // ---- epilogue: 8 voxels x 8 couts -> 2 float4 stores per voxel ----
    #pragma unroll
    for (int q = 0; q < 8; ++q) {
        float4 oa, ob;
        unpack2(acc[q][0], oa.x, oa.y);
        unpack2(acc[q][1], oa.z, oa.w);
        unpack2(acc[q][2], ob.x, ob.y);
        unpack2(acc[q][3], ob.z, ob.w);
        float* orow = out + (size_t)(jbase + v0 + q) * COUT + c0;
        *reinterpret_cast<float4*>(orow)     = oa;
        *reinterpret_cast<float4*>(orow + 4) = ob;
    }
}

extern "C" void kernel_launch(void* const* d_in, const int* in_sizes, int n_in,
                              void* d_out, int out_size) {
    const float* feats  = (const float*)d_in[0];   // [N, 64] f32
    const float* weight = (const float*)d_in[1];   // [27, 64, 64] f32
    const float* bias   = (const float*)d_in[2];   // [64] f32
    const int*   nbr    = (const int*)  d_in[3];   // [27, N] i32
    float*       out    = (float*)d_out;           // [N, 64] f32

    static bool attr_set = false;
    if (!attr_set) {
        cudaFuncSetAttribute(spconv88_kernel,
                             cudaFuncAttributeMaxDynamicSharedMemorySize, SMEM_BYTES);
        attr_set = true;
    }
    spconv88_kernel<<<NV / TILE, THREADS, SMEM_BYTES>>>(feats, weight, bias, nbr, out);
}

// round 4
// speedup vs baseline: 1.6506x; 1.6374x over previous
#include <cuda_runtime.h>
#include <cstdint>

#define NV      400000
#define CIN     64
#define COUT    64
#define KT      27
#define TILE_M  256
#define THREADS 256

#define FS_PAD 68      // Fs row stride in words  (bank: 68 % 32 = 4)
#define WS_PAD 72      // Ws row stride in words  (bank: 72 % 32 = 8)
#define SMEM_WORDS (TILE_M * FS_PAD + CIN * WS_PAD)
#define SMEM_BYTES (SMEM_WORDS * 4)

__device__ __forceinline__ uint32_t cvt_tf32(float x) {
    uint32_t u;
    asm("cvt.rna.tf32.f32 %0, %1;" : "=r"(u) : "f"(x));
    return u;
}

__device__ __forceinline__ void mma_tf32(float* d, const uint32_t* a, const uint32_t* b) {
    asm volatile(
        "mma.sync.aligned.m16n8k8.row.col.f32.tf32.tf32.f32 "
        "{%0,%1,%2,%3}, {%4,%5,%6,%7}, {%8,%9}, {%0,%1,%2,%3};"
        : "+f"(d[0]), "+f"(d[1]), "+f"(d[2]), "+f"(d[3])
        : "r"(a[0]), "r"(a[1]), "r"(a[2]), "r"(a[3]), "r"(b[0]), "r"(b[1]));
}

// CTA: 256 threads = 8 warps, tile M=256 voxels x N=64 couts.
// Warp grid 4(M) x 2(N); warp tile 64x32 = 4 mtiles(16) x 4 ntiles(8).
__global__ __launch_bounds__(THREADS, 2)
void spconv_hmma(const float* __restrict__ feats,
                 const float* __restrict__ weight,
                 const float* __restrict__ bias,
                 const int*   __restrict__ nbr,
                 float*       __restrict__ out)
{
    extern __shared__ uint32_t smem[];
    uint32_t* Fs = smem;                       // [256][FS_PAD] tf32 activations
    uint32_t* Ws = smem + TILE_M * FS_PAD;     // [64][WS_PAD]  tf32 weights [k][n]

    const int tid  = threadIdx.x;
    const int warp = tid >> 5;
    const int lane = tid & 31;
    const int lq   = lane >> 2;                // 0..7
    const int lr   = lane & 3;                 // 0..3

    const int mq = warp >> 1;                  // 0..3 : M quadrant (64 voxels)
    const int nh = warp & 1;                   // 0..1 : N half (32 couts)
    const int vb = mq * 64;
    const int nb = nh * 32;

    const int jbase = blockIdx.x * TILE_M;

    // gather geometry: 16 lanes per voxel row, 16 rows per pass
    const int f4   = tid & 15;
    const int vrow = tid >> 4;

    float acc[4][4][4];
    #pragma unroll
    for (int mt = 0; mt < 4; ++mt)
        #pragma unroll
        for (int nt = 0; nt < 4; ++nt)
            #pragma unroll
            for (int e = 0; e < 4; ++e) acc[mt][nt][e] = 0.f;

    const float4* feats4 = reinterpret_cast<const float4*>(feats);

    for (int k = 0; k < KT; ++k) {
        __syncthreads();   // previous tap's fragment reads complete

        // ---- stage weights: W[k][cin][cout] -> Ws[cin_k][cout_n], tf32 ----
        const float4* wk = reinterpret_cast<const float4*>(weight + k * (CIN * COUT));
        #pragma unroll
        for (int r = 0; r < 4; ++r) {
            const int l  = tid + r * THREADS;          // 0..1023
            const int kk = l >> 4;
            const int n4 = l & 15;
            const float4 w = __ldg(wk + l);
            uint4 u;
            u.x = cvt_tf32(w.x); u.y = cvt_tf32(w.y);
            u.z = cvt_tf32(w.z); u.w = cvt_tf32(w.w);
            *reinterpret_cast<uint4*>(&Ws[kk * WS_PAD + n4 * 4]) = u;
        }

        // ---- coalesced masked gather into Fs (tf32) ----
        const int* nk = nbr + (size_t)k * NV;
        #pragma unroll
        for (int it = 0; it < 16; ++it) {
            const int v = vrow + 16 * it;              // voxel within tile
            const int j = jbase + v;
            int idx = -1;
            if (j < NV) idx = __ldg(nk + j);
            float4 val = make_float4(0.f, 0.f, 0.f, 0.f);
            if (idx >= 0) val = __ldg(feats4 + (size_t)idx * 16 + f4);
            uint4 u;
            u.x = cvt_tf32(val.x); u.y = cvt_tf32(val.y);
            u.z = cvt_tf32(val.z); u.w = cvt_tf32(val.w);
            *reinterpret_cast<uint4*>(&Fs[v * FS_PAD + f4 * 4]) = u;
        }
        __syncthreads();

        // ---- warp-tile GEMM: K=64 in 8 steps of k=8 ----
        #pragma unroll
        for (int ks = 0; ks < 8; ++ks) {
            const int kb = ks * 8;

            uint32_t b[4][2];
            #pragma unroll
            for (int nt = 0; nt < 4; ++nt) {
                const int ncol = nb + nt * 8 + lq;
                b[nt][0] = Ws[(kb + lr)     * WS_PAD + ncol];
                b[nt][1] = Ws[(kb + lr + 4) * WS_PAD + ncol];
            }
            #pragma unroll
            for (int mt = 0; mt < 4; ++mt) {
                uint32_t a[4];
                const int base = (vb + mt * 16 + lq) * FS_PAD + kb + lr;
                a[0] = Fs[base];
                a[1] = Fs[base + 8 * FS_PAD];
                a[2] = Fs[base + 4];
                a[3] = Fs[base + 8 * FS_PAD + 4];
                #pragma unroll
                for (int nt = 0; nt < 4; ++nt)
                    mma_tf32(acc[mt][nt], a, b[nt]);
            }
        }
    }

    // ---- epilogue: add bias, store float2 per c-pair ----
    #pragma unroll
    for (int nt = 0; nt < 4; ++nt) {
        const int col = nb + nt * 8 + lr * 2;
        const float bx = __ldg(bias + col);
        const float by = __ldg(bias + col + 1);
        #pragma unroll
        for (int mt = 0; mt < 4; ++mt) {
            const int r0 = jbase + vb + mt * 16 + lq;
            if (r0 < NV) {
                float2 o = make_float2(acc[mt][nt][0] + bx, acc[mt][nt][1] + by);
                *reinterpret_cast<float2*>(out + (size_t)r0 * COUT + col) = o;
            }
            const int r1 = r0 + 8;
            if (r1 < NV) {
                float2 o = make_float2(acc[mt][nt][2] + bx, acc[mt][nt][3] + by);
                *reinterpret_cast<float2*>(out + (size_t)r1 * COUT + col) = o;
            }
        }
    }
}

extern "C" void kernel_launch(void* const* d_in, const int* in_sizes, int n_in,
                              void* d_out, int out_size) {
    const float* feats  = (const float*)d_in[0];   // [N, 64] f32
    const float* weight = (const float*)d_in[1];   // [27, 64, 64] f32
    const float* bias   = (const float*)d_in[2];   // [64] f32
    const int*   nbr    = (const int*)  d_in[3];   // [27, N] i32
    float*       out    = (float*)d_out;           // [N, 64] f32

    static bool init_done = false;
    if (!init_done) {
        cudaFuncSetAttribute(spconv_hmma,
                             cudaFuncAttributeMaxDynamicSharedMemorySize, SMEM_BYTES);
        init_done = true;
    }
    const int grid = (NV + TILE_M - 1) / TILE_M;   // 1563
    spconv_hmma<<<grid, THREADS, SMEM_BYTES>>>(feats, weight, bias, nbr, out);
}

// round 6
// speedup vs baseline: 3.1943x; 1.9353x over previous
#include <cuda_runtime.h>
#include <cstdint>

#define NV      400000
#define CIN     64
#define COUT    64
#define KT      27
#define TILE_M  128
#define THREADS 256

#define FS_PAD 68      // Fs row stride (words)
#define WS_PAD 72      // Ws row stride (words)
#define FS_WORDS (TILE_M * FS_PAD)   // 8704
#define WS_WORDS (CIN * WS_PAD)      // 4608
#define BUF_WORDS (FS_WORDS + WS_WORDS)
#define SMEM_BYTES (2 * BUF_WORDS * 4)   // 106496

// ---------------- device globals: pre-converted tf32 copies ----------------
__device__ float g_feats[(size_t)NV * CIN];
__device__ float g_w[KT * CIN * COUT];

__device__ __forceinline__ uint32_t cvt_tf32(float x) {
    uint32_t u;
    asm("cvt.rna.tf32.f32 %0, %1;" : "=r"(u) : "f"(x));
    return u;
}
__device__ __forceinline__ uint32_t smem_u32(const void* p) {
    uint32_t a;
    asm("{ .reg .u64 t; cvta.to.shared.u64 t, %1; cvt.u32.u64 %0, t; }" : "=r"(a) : "l"(p));
    return a;
}
__device__ __forceinline__ void cp_async16(uint32_t dst, const void* src, uint32_t src_bytes) {
    asm volatile("cp.async.cg.shared.global [%0], [%1], 16, %2;"
                 :: "r"(dst), "l"(src), "r"(src_bytes) : "memory");
}
__device__ __forceinline__ void cp_commit() {
    asm volatile("cp.async.commit_group;" ::: "memory");
}
template <int N>
__device__ __forceinline__ void cp_wait() {
    asm volatile("cp.async.wait_group %0;" :: "n"(N) : "memory");
}
__device__ __forceinline__ void mma_tf32(float* d, const uint32_t* a, const uint32_t* b) {
    asm volatile(
        "mma.sync.aligned.m16n8k8.row.col.f32.tf32.tf32.f32 "
        "{%0,%1,%2,%3}, {%4,%5,%6,%7}, {%8,%9}, {%0,%1,%2,%3};"
        : "+f"(d[0]), "+f"(d[1]), "+f"(d[2]), "+f"(d[3])
        : "r"(a[0]), "r"(a[1]), "r"(a[2]), "r"(a[3]), "r"(b[0]), "r"(b[1]));
}

// ---------------- prep kernels (tf32 round once) ----------------
__global__ void prep_feats(const float4* __restrict__ f) {
    size_t i = (size_t)blockIdx.x * 256 + threadIdx.x;   // NV*CIN/4 chunks
    const float4 v = f[i];
    uint4 u;
    u.x = cvt_tf32(v.x); u.y = cvt_tf32(v.y);
    u.z = cvt_tf32(v.z); u.w = cvt_tf32(v.w);
    reinterpret_cast<uint4*>(g_feats)[i] = u;
}
__global__ void prep_w(const float* __restrict__ w) {
    int i = blockIdx.x * 256 + threadIdx.x;              // KT*CIN*COUT
    g_w[i] = __uint_as_float(cvt_tf32(w[i]));
}

// ---------------- main kernel ----------------
// CTA: 256 threads = 8 warps over tile M=128 x N=64. Warp grid 4(M) x 2(N),
// warp tile 32x32 = 2 mtiles x 4 ntiles. Double-buffered cp.async pipeline.
__global__ __launch_bounds__(THREADS, 2)
void spconv_pipe(const float* __restrict__ bias,
                 const int*   __restrict__ nbr,
                 float*       __restrict__ out)
{
    extern __shared__ uint32_t smem[];
    const uint32_t smem_base = smem_u32(smem);

    const int tid  = threadIdx.x;
    const int warp = tid >> 5;
    const int lane = tid & 31;
    const int lq   = lane >> 2;
    const int lr   = lane & 3;
    const int vb   = (warp >> 1) * 32;
    const int nb   = (warp & 1) * 32;
    const int jbase = blockIdx.x * TILE_M;

    // staging geometry: 2 threads per voxel row, 8 interleaved 16B chunks each
    const int srow = tid >> 1;          // 0..127
    const int spar = tid & 1;

    float acc[2][4][4];
    #pragma unroll
    for (int mt = 0; mt < 2; ++mt)
        #pragma unroll
        for (int nt = 0; nt < 4; ++nt)
            #pragma unroll
            for (int e = 0; e < 4; ++e) acc[mt][nt][e] = 0.f;

    // ---- staging helper ----
    auto stage = [&](int k, int buf, int idx) {
        const uint32_t fbase = smem_base + (buf * BUF_WORDS) * 4;
        const uint32_t wbase = fbase + FS_WORDS * 4;
        // A: voxel row srow, chunks spar + 2i; invalid neighbor -> zero-fill
        const uint32_t row_sz = (idx >= 0) ? 16u : 0u;
        const int safe = idx < 0 ? 0 : idx;
        const float* src = g_feats + (size_t)safe * CIN;
        const uint32_t dst0 = fbase + (srow * FS_PAD) * 4;
        #pragma unroll
        for (int i = 0; i < 8; ++i) {
            const int c = spar + 2 * i;          // float4 chunk 0..15
            cp_async16(dst0 + c * 16, src + c * 4, row_sz);
        }
        // W: 1024 float4 chunks, 4 per thread
        const float* wsrc = g_w + (size_t)k * (CIN * COUT);
        #pragma unroll
        for (int r = 0; r < 4; ++r) {
            const int l = tid + r * THREADS;
            cp_async16(wbase + ((l >> 4) * WS_PAD + (l & 15) * 4) * 4,
                       wsrc + l * 4, 16u);
        }
    };

    // prologue: stage tap 0, prefetch idx for tap 1
    int idx_cur = __ldg(nbr + jbase + srow);                       // tap 0
    stage(0, 0, idx_cur);
    cp_commit();
    int idx_nxt = __ldg(nbr + (size_t)NV + jbase + srow);          // tap 1

    for (int k = 0; k < KT; ++k) {
        const int cb = k & 1;            // compute buffer
        __syncthreads();                 // everyone done reading buffer cb (tap k-2)

        if (k + 1 < KT) {
            stage(k + 1, cb ^ 1, idx_nxt);
            cp_commit();
            if (k + 2 < KT)
                idx_nxt = __ldg(nbr + (size_t)(k + 2) * NV + jbase + srow);
            cp_wait<1>();                // buffer cb (staged last iter) ready
        } else {
            cp_wait<0>();
        }
        __syncthreads();

        // ---- compute tap k from buffer cb ----
        const uint32_t* Fs = smem + cb * BUF_WORDS;
        const uint32_t* Ws = Fs + FS_WORDS;
        #pragma unroll
        for (int ks = 0; ks < 8; ++ks) {
            const int kb = ks * 8;
            uint32_t b[4][2];
            #pragma unroll
            for (int nt = 0; nt < 4; ++nt) {
                const int ncol = nb + nt * 8 + lq;
                b[nt][0] = Ws[(kb + lr)     * WS_PAD + ncol];
                b[nt][1] = Ws[(kb + lr + 4) * WS_PAD + ncol];
            }
            #pragma unroll
            for (int mt = 0; mt < 2; ++mt) {
                uint32_t a[4];
                const int base = (vb + mt * 16 + lq) * FS_PAD + kb + lr;
                a[0] = Fs[base];
                a[1] = Fs[base + 8 * FS_PAD];
                a[2] = Fs[base + 4];
                a[3] = Fs[base + 8 * FS_PAD + 4];
                #pragma unroll
                for (int nt = 0; nt < 4; ++nt)
                    mma_tf32(acc[mt][nt], a, b[nt]);
            }
        }
    }

    // ---- epilogue: add bias, store float2 pairs ----
    #pragma unroll
    for (int nt = 0; nt < 4; ++nt) {
        const int col = nb + nt * 8 + lr * 2;
        const float bx = __ldg(bias + col);
        const float by = __ldg(bias + col + 1);
        #pragma unroll
        for (int mt = 0; mt < 2; ++mt) {
            const int r0 = jbase + vb + mt * 16 + lq;
            float2 o0 = make_float2(acc[mt][nt][0] + bx, acc[mt][nt][1] + by);
            float2 o1 = make_float2(acc[mt][nt][2] + bx, acc[mt][nt][3] + by);
            *reinterpret_cast<float2*>(out + (size_t)r0 * COUT + col)       = o0;
            *reinterpret_cast<float2*>(out + (size_t)(r0 + 8) * COUT + col) = o1;
        }
    }
}

extern "C" void kernel_launch(void* const* d_in, const int* in_sizes, int n_in,
                              void* d_out, int out_size) {
    const float* feats  = (const float*)d_in[0];   // [N, 64] f32
    const float* weight = (const float*)d_in[1];   // [27, 64, 64] f32
    const float* bias   = (const float*)d_in[2];   // [64] f32
    const int*   nbr    = (const int*)  d_in[3];   // [27, N] i32
    float*       out    = (float*)d_out;           // [N, 64] f32

    static bool init_done = false;
    if (!init_done) {
        cudaFuncSetAttribute(spconv_pipe,
                             cudaFuncAttributeMaxDynamicSharedMemorySize, SMEM_BYTES);
        init_done = true;
    }
    prep_feats<<<(NV * CIN / 4) / 256, 256>>>(reinterpret_cast<const float4*>(feats));
    prep_w<<<(KT * CIN * COUT) / 256, 256>>>(weight);
    spconv_pipe<<<NV / TILE_M, THREADS, SMEM_BYTES>>>(bias, nbr, out);
}

// round 7
// speedup vs baseline: 3.5253x; 1.1036x over previous
#include <cuda_runtime.h>
#include <cstdint>

#define NV      400000
#define CIN     64
#define COUT    64
#define KT      27
#define TILE_M  256
#define THREADS 256

#define FS_PAD 68      // Fs row stride (words)
#define WS_PAD 72      // Ws row stride (words)
#define FS_WORDS (TILE_M * FS_PAD)   // 17408
#define WS_WORDS (CIN * WS_PAD)      // 4608
#define BUF_WORDS (FS_WORDS + WS_WORDS)
#define SMEM_BYTES (2 * BUF_WORDS * 4)   // 176128

// ---------------- device globals: pre-converted tf32 copies ----------------
__device__ float g_feats[(size_t)NV * CIN];
__device__ float g_w[KT * CIN * COUT];

__device__ __forceinline__ uint32_t cvt_tf32(float x) {
    uint32_t u;
    asm("cvt.rna.tf32.f32 %0, %1;" : "=r"(u) : "f"(x));
    return u;
}
__device__ __forceinline__ uint32_t smem_u32(const void* p) {
    uint32_t a;
    asm("{ .reg .u64 t; cvta.to.shared.u64 t, %1; cvt.u32.u64 %0, t; }" : "=r"(a) : "l"(p));
    return a;
}
__device__ __forceinline__ void cp_async16(uint32_t dst, const void* src, uint32_t src_bytes) {
    asm volatile("cp.async.cg.shared.global [%0], [%1], 16, %2;"
                 :: "r"(dst), "l"(src), "r"(src_bytes) : "memory");
}
__device__ __forceinline__ void cp_commit() {
    asm volatile("cp.async.commit_group;" ::: "memory");
}
template <int N>
__device__ __forceinline__ void cp_wait() {
    asm volatile("cp.async.wait_group %0;" :: "n"(N) : "memory");
}
__device__ __forceinline__ void mma_tf32(float* d, const uint32_t* a, const uint32_t* b) {
    asm volatile(
        "mma.sync.aligned.m16n8k8.row.col.f32.tf32.tf32.f32 "
        "{%0,%1,%2,%3}, {%4,%5,%6,%7}, {%8,%9}, {%0,%1,%2,%3};"
        : "+f"(d[0]), "+f"(d[1]), "+f"(d[2]), "+f"(d[3])
        : "r"(a[0]), "r"(a[1]), "r"(a[2]), "r"(a[3]), "r"(b[0]), "r"(b[1]));
}

// ---------------- prep kernels (tf32 round once) ----------------
__global__ void prep_feats(const float4* __restrict__ f) {
    size_t i = (size_t)blockIdx.x * 256 + threadIdx.x;   // NV*CIN/4 chunks
    const float4 v = f[i];
    uint4 u;
    u.x = cvt_tf32(v.x); u.y = cvt_tf32(v.y);
    u.z = cvt_tf32(v.z); u.w = cvt_tf32(v.w);
    reinterpret_cast<uint4*>(g_feats)[i] = u;
}
__global__ void prep_w(const float* __restrict__ w) {
    int i = blockIdx.x * 256 + threadIdx.x;              // KT*CIN*COUT
    g_w[i] = __uint_as_float(cvt_tf32(w[i]));
}

// ---------------- main kernel ----------------
// CTA: 256 threads = 8 warps, tile M=256 x N=64. Warp grid 4(M) x 2(N),
// warp tile 64x32 = 4 mtiles(16) x 4 ntiles(8). cp.async double buffer.
__global__ __launch_bounds__(THREADS, 1)
void spconv_pipe(const float* __restrict__ bias,
                 const int*   __restrict__ nbr,
                 float*       __restrict__ out)
{
    extern __shared__ uint32_t smem[];
    const uint32_t smem_base = smem_u32(smem);

    const int tid  = threadIdx.x;
    const int warp = tid >> 5;
    const int lane = tid & 31;
    const int lq   = lane >> 2;
    const int lr   = lane & 3;
    const int vb   = (warp >> 1) * 64;       // M quadrant (64 voxels)
    const int nb   = (warp & 1) * 32;        // N half (32 couts)
    const int jbase = blockIdx.x * TILE_M;

    // staging: thread tid owns voxel row tid (16 x 16B chunks)
    const int jrow = jbase + tid;
    const bool row_ok = jrow < NV;

    float acc[4][4][4];
    #pragma unroll
    for (int mt = 0; mt < 4; ++mt)
        #pragma unroll
        for (int nt = 0; nt < 4; ++nt)
            #pragma unroll
            for (int e = 0; e < 4; ++e) acc[mt][nt][e] = 0.f;

    // ---- staging helper ----
    auto stage = [&](int k, int buf, int idx) {
        const uint32_t fbase = smem_base + (buf * BUF_WORDS) * 4;
        const uint32_t wbase = fbase + FS_WORDS * 4;
        const uint32_t row_sz = (idx >= 0) ? 16u : 0u;   // zero-fill invalid/overflow
        const int safe = idx < 0 ? 0 : idx;
        const float* src = g_feats + (size_t)safe * CIN;
        const uint32_t dst0 = fbase + (tid * FS_PAD) * 4;
        #pragma unroll
        for (int c = 0; c < 16; ++c)
            cp_async16(dst0 + c * 16, src + c * 4, row_sz);
        const float* wsrc = g_w + (size_t)k * (CIN * COUT);
        #pragma unroll
        for (int r = 0; r < 4; ++r) {
            const int l = tid + r * THREADS;
            cp_async16(wbase + ((l >> 4) * WS_PAD + (l & 15) * 4) * 4,
                       wsrc + l * 4, 16u);
        }
    };
    auto load_idx = [&](int k) -> int {
        return row_ok ? __ldg(nbr + (size_t)k * NV + jrow) : -1;
    };

    // prologue
    stage(0, 0, load_idx(0));
    cp_commit();
    int idx_nxt = load_idx(1);

    for (int k = 0; k < KT; ++k) {
        const int cb = k & 1;
        __syncthreads();                 // done reading buffer cb (tap k-2)

        if (k + 1 < KT) {
            stage(k + 1, cb ^ 1, idx_nxt);
            cp_commit();
            if (k + 2 < KT) idx_nxt = load_idx(k + 2);
            cp_wait<1>();
        } else {
            cp_wait<0>();
        }
        __syncthreads();

        const uint32_t* Fs = smem + cb * BUF_WORDS;
        const uint32_t* Ws = Fs + FS_WORDS;
        #pragma unroll
        for (int ks = 0; ks < 8; ++ks) {
            const int kb = ks * 8;
            uint32_t b[4][2];
            #pragma unroll
            for (int nt = 0; nt < 4; ++nt) {
                const int ncol = nb + nt * 8 + lq;
                b[nt][0] = Ws[(kb + lr)     * WS_PAD + ncol];
                b[nt][1] = Ws[(kb + lr + 4) * WS_PAD + ncol];
            }
            #pragma unroll
            for (int mt = 0; mt < 4; ++mt) {
                uint32_t a[4];
                const int base = (vb + mt * 16 + lq) * FS_PAD + kb + lr;
                a[0] = Fs[base];
                a[1] = Fs[base + 8 * FS_PAD];
                a[2] = Fs[base + 4];
                a[3] = Fs[base + 8 * FS_PAD + 4];
                #pragma unroll
                for (int nt = 0; nt < 4; ++nt)
                    mma_tf32(acc[mt][nt], a, b[nt]);
            }
        }
    }

    // ---- epilogue: add bias, store float2 pairs (guarded for last tile) ----
    #pragma unroll
    for (int nt = 0; nt < 4; ++nt) {
        const int col = nb + nt * 8 + lr * 2;
        const float bx = __ldg(bias + col);
        const float by = __ldg(bias + col + 1);
        #pragma unroll
        for (int mt = 0; mt < 4; ++mt) {
            const int r0 = jbase + vb + mt * 16 + lq;
            if (r0 < NV) {
                float2 o = make_float2(acc[mt][nt][0] + bx, acc[mt][nt][1] + by);
                *reinterpret_cast<float2*>(out + (size_t)r0 * COUT + col) = o;
            }
            if (r0 + 8 < NV) {
                float2 o = make_float2(acc[mt][nt][2] + bx, acc[mt][nt][3] + by);
                *reinterpret_cast<float2*>(out + (size_t)(r0 + 8) * COUT + col) = o;
            }
        }
    }
}

extern "C" void kernel_launch(void* const* d_in, const int* in_sizes, int n_in,
                              void* d_out, int out_size) {
    const float* feats  = (const float*)d_in[0];   // [N, 64] f32
    const float* weight = (const float*)d_in[1];   // [27, 64, 64] f32
    const float* bias   = (const float*)d_in[2];   // [64] f32
    const int*   nbr    = (const int*)  d_in[3];   // [27, N] i32
    float*       out    = (float*)d_out;           // [N, 64] f32

    static bool init_done = false;
    if (!init_done) {
        cudaFuncSetAttribute(spconv_pipe,
                             cudaFuncAttributeMaxDynamicSharedMemorySize, SMEM_BYTES);
        init_done = true;
    }
    prep_feats<<<(NV * CIN / 4) / 256, 256>>>(reinterpret_cast<const float4*>(feats));
    prep_w<<<(KT * CIN * COUT) / 256, 256>>>(weight);
    const int grid = (NV + TILE_M - 1) / TILE_M;   // 1563
    spconv_pipe<<<grid, THREADS, SMEM_BYTES>>>(bias, nbr, out);
}